// round 1
// baseline (speedup 1.0000x reference)
#include <cuda_runtime.h>
#include <math.h>

#define BSZ 8
#define CIN 64
#define MID 32
#define HH 256
#define WW 256
#define TS 16
#define PS 18            // TS + 2 halo
#define PP (PS*PS)       // 324
#define BN_EPS 1e-5f

// selection results (written by sel_k, read by fused_k; same-stream ordering)
__device__ int   g_sel_src[CIN];
__device__ float g_sel_scale[CIN];

// ---------------------------------------------------------------------------
// Kernel 1: top-64 of c_score[128], stable tie-break (matches lax.top_k).
// ---------------------------------------------------------------------------
__global__ void sel_k(const float* __restrict__ cs) {
    int j = threadIdx.x;                 // 0..127
    float key = cs[j];
    int rank = 0;
#pragma unroll 16
    for (int i = 0; i < 2 * CIN; i++) {
        float vi = cs[i];
        rank += (vi > key || (vi == key && i < j)) ? 1 : 0;
    }
    if (rank < CIN) {
        g_sel_src[rank]   = j;
        g_sel_scale[rank] = 1.0f / (1.0f + expf(-key));
    }
}

// ---------------------------------------------------------------------------
// Kernel 2: fully fused inception block for one 16x16 tile.
// smem: x patch (64x18x18), t1 patch (32x18x18, = BN(1x1 conv) for inner 3x3),
//       ta patch (32x18x18, = BN(1x1 conv) for avgpool), staged 1x1 weights,
//       per-channel weight buffer.
// ---------------------------------------------------------------------------
#define SMEM_FLOATS (CIN*PP + 2*MID*PP + 2*MID*CIN + CIN*9)
#define SMEM_BYTES  (SMEM_FLOATS * 4)

extern __shared__ float smem[];

__global__ __launch_bounds__(256, 1)
void fused_k(const float* __restrict__ x,
             const float* __restrict__ w_main, const float* __restrict__ bn_main,
             const float* __restrict__ w_1x1,  const float* __restrict__ bn_1x1,
             const float* __restrict__ w31,    const float* __restrict__ bn31,
             const float* __restrict__ w32,    const float* __restrict__ bn32,
             const float* __restrict__ wavg,   const float* __restrict__ bnavg1,
             const float* __restrict__ bnavg2,
             float* __restrict__ out)
{
    float* xs   = smem;                  // CIN*PP
    float* t1s  = xs  + CIN * PP;        // MID*PP
    float* tas  = t1s + MID * PP;        // MID*PP
    float* w1s  = tas + MID * PP;        // MID*CIN
    float* was  = w1s + MID * CIN;       // MID*CIN
    float* wbuf = was + MID * CIN;       // CIN*9 = 576

    const int tid = threadIdx.x;
    const int b   = blockIdx.z;
    const int h0  = blockIdx.y * TS;
    const int w0  = blockIdx.x * TS;

    // ---- load x patch (zero outside image = conv zero padding) ----
    const float* xb = x + (size_t)b * CIN * HH * WW;
    for (int i = tid; i < CIN * PP; i += 256) {
        int ic = i / PP;
        int p  = i - ic * PP;
        int py = p / PS, px = p - py * PS;
        int gh = h0 + py - 1, gw = w0 + px - 1;
        float v = 0.0f;
        if ((unsigned)gh < HH && (unsigned)gw < WW)
            v = xb[(ic * HH + gh) * WW + gw];
        xs[i] = v;
    }
    // ---- stage the two 1x1 weight matrices ----
    for (int i = tid; i < MID * CIN; i += 256) {
        w1s[i] = w31[i];
        was[i] = wavg[i];
    }
    __syncthreads();

    // ---- compute t1 (BN(conv1x1)) and ta (BN(conv1x1)) over the full patch ----
    for (int p = tid; p < PP; p += 256) {
        int py = p / PS, px = p - py * PS;
        int gh = h0 + py - 1, gw = w0 + px - 1;
        bool inimg = ((unsigned)gh < HH) && ((unsigned)gw < WW);
        if (!inimg) {
            // zero = conv3x3's zero-padding of t1, and reduce_window's zero pad for ta
#pragma unroll 4
            for (int oc = 0; oc < MID; oc++) { t1s[oc*PP + p] = 0.0f; tas[oc*PP + p] = 0.0f; }
        } else {
            for (int oc = 0; oc < MID; oc += 2) {
                float a0 = 0.f, a1 = 0.f, c0 = 0.f, c1 = 0.f;
                const float* wr0 = &w1s[oc * CIN];
                const float* wr1 = &w1s[(oc + 1) * CIN];
                const float* vr0 = &was[oc * CIN];
                const float* vr1 = &was[(oc + 1) * CIN];
#pragma unroll 8
                for (int ic = 0; ic < CIN; ic++) {
                    float xv = xs[ic * PP + p];
                    a0 += xv * wr0[ic];
                    a1 += xv * wr1[ic];
                    c0 += xv * vr0[ic];
                    c1 += xv * vr1[ic];
                }
                {
                    float g = bn31[oc],   be = bn31[32+oc],   m = bn31[64+oc],   vv = bn31[96+oc];
                    float inv = g * rsqrtf(vv + BN_EPS);
                    t1s[oc*PP + p] = a0 * inv + (be - m * inv);
                    g = bn31[oc+1]; be = bn31[33+oc]; m = bn31[65+oc]; vv = bn31[97+oc];
                    inv = g * rsqrtf(vv + BN_EPS);
                    t1s[(oc+1)*PP + p] = a1 * inv + (be - m * inv);
                }
                {
                    float g = bnavg1[oc], be = bnavg1[32+oc], m = bnavg1[64+oc], vv = bnavg1[96+oc];
                    float inv = g * rsqrtf(vv + BN_EPS);
                    tas[oc*PP + p] = c0 * inv + (be - m * inv);
                    g = bnavg1[oc+1]; be = bnavg1[33+oc]; m = bnavg1[65+oc]; vv = bnavg1[97+oc];
                    inv = g * rsqrtf(vv + BN_EPS);
                    tas[(oc+1)*PP + p] = c1 * inv + (be - m * inv);
                }
            }
        }
    }
    __syncthreads();

    // ---- per selected output channel: compute one branch value per pixel ----
    const int ty = tid >> 4, tx = tid & 15;
    float* outb = out + (size_t)b * CIN * HH * WW;

    for (int s = 0; s < CIN; s++) {
        int   src   = g_sel_src[s];
        float scale = g_sel_scale[s];
        int   br    = src >> 5;
        int   c     = src & 31;

        // stage this channel's weights
        if (br == 0) {
            const float* wsrc = w_main + c * CIN * 9;
            for (int i = tid; i < CIN * 9; i += 256) wbuf[i] = wsrc[i];
        } else if (br == 2) {
            const float* wsrc = w32 + c * MID * 9;
            if (tid < MID * 9) wbuf[tid] = wsrc[tid];
            if (tid < MID * 9 - 256) wbuf[256 + tid] = wsrc[256 + tid];
        } else if (br == 1) {
            if (tid < CIN) wbuf[tid] = w_1x1[c * CIN + tid];
        }
        __syncthreads();

        float acc;
        const float* bnp;
        if (br == 0) {
            bnp = bn_main;
            float a0 = 0.f, a1 = 0.f;
#pragma unroll 4
            for (int ic = 0; ic < CIN; ic++) {
                const float* xr = &xs[ic * PP + ty * PS + tx];
                const float* wr = &wbuf[ic * 9];
                a0 += xr[0]      * wr[0] + xr[1]      * wr[1] + xr[2]      * wr[2];
                a1 += xr[PS]     * wr[3] + xr[PS+1]   * wr[4] + xr[PS+2]   * wr[5];
                a0 += xr[2*PS]   * wr[6] + xr[2*PS+1] * wr[7] + xr[2*PS+2] * wr[8];
            }
            acc = a0 + a1;
        } else if (br == 1) {
            bnp = bn_1x1;
            const int pc = (ty + 1) * PS + (tx + 1);
            float a0 = 0.f, a1 = 0.f;
#pragma unroll 8
            for (int ic = 0; ic < CIN; ic += 2) {
                a0 += xs[ic * PP + pc]       * wbuf[ic];
                a1 += xs[(ic + 1) * PP + pc] * wbuf[ic + 1];
            }
            acc = a0 + a1;
        } else if (br == 2) {
            bnp = bn32;
            float a0 = 0.f, a1 = 0.f;
#pragma unroll 4
            for (int ic = 0; ic < MID; ic++) {
                const float* xr = &t1s[ic * PP + ty * PS + tx];
                const float* wr = &wbuf[ic * 9];
                a0 += xr[0]      * wr[0] + xr[1]      * wr[1] + xr[2]      * wr[2];
                a1 += xr[PS]     * wr[3] + xr[PS+1]   * wr[4] + xr[PS+2]   * wr[5];
                a0 += xr[2*PS]   * wr[6] + xr[2*PS+1] * wr[7] + xr[2*PS+2] * wr[8];
            }
            acc = a0 + a1;
        } else {
            bnp = bnavg2;
            const float* xr = &tas[c * PP + ty * PS + tx];
            acc = (xr[0] + xr[1] + xr[2]
                 + xr[PS] + xr[PS+1] + xr[PS+2]
                 + xr[2*PS] + xr[2*PS+1] + xr[2*PS+2]) * (1.0f / 9.0f);
        }

        float g  = bnp[c], be = bnp[32 + c], m = bnp[64 + c], vv = bnp[96 + c];
        float inv = g * rsqrtf(vv + BN_EPS);
        float val = (acc * inv + (be - m * inv)) * scale;
        outb[((size_t)s * HH + (h0 + ty)) * WW + (w0 + tx)] = val;
        __syncthreads();   // protect wbuf before next stage
    }
}

// ---------------------------------------------------------------------------
extern "C" void kernel_launch(void* const* d_in, const int* in_sizes, int n_in,
                              void* d_out, int out_size) {
    const float* x       = (const float*)d_in[0];
    const float* w_main  = (const float*)d_in[1];
    const float* bn_main = (const float*)d_in[2];
    const float* w_1x1   = (const float*)d_in[3];
    const float* bn_1x1  = (const float*)d_in[4];
    const float* w31     = (const float*)d_in[5];
    const float* bn31    = (const float*)d_in[6];
    const float* w32     = (const float*)d_in[7];
    const float* bn32    = (const float*)d_in[8];
    const float* wavg    = (const float*)d_in[9];
    const float* bnavg1  = (const float*)d_in[10];
    const float* bnavg2  = (const float*)d_in[11];
    const float* c_score = (const float*)d_in[12];
    float* out = (float*)d_out;

    cudaFuncSetAttribute(fused_k, cudaFuncAttributeMaxDynamicSharedMemorySize, SMEM_BYTES);

    sel_k<<<1, 2 * CIN>>>(c_score);

    dim3 grid(WW / TS, HH / TS, BSZ);
    fused_k<<<grid, 256, SMEM_BYTES>>>(x, w_main, bn_main, w_1x1, bn_1x1,
                                       w31, bn31, w32, bn32,
                                       wavg, bnavg1, bnavg2, out);
}

// round 2
// speedup vs baseline: 2.2448x; 2.2448x over previous
#include <cuda_runtime.h>
#include <math.h>

#define BSZ 8
#define CIN 64
#define MID 32
#define HH 256
#define WW 256
#define TS 16
#define PS 18            // TS + 2 halo
#define PP 324           // PS*PS
#define BN_EPS 1e-5f

// ---- selection metadata (sel_k -> fused_k, same-stream ordering) ----
__device__ int   g_src[64];
__device__ float g_scale[64];
__device__ int   g_br[64];
__device__ int   g_c[64];
__device__ int   g_slot[64];     // slot in tas for avg-branch channels
__device__ int   g_ng3;          // padded group count for ta phase-1
__device__ int   g_list3[32];    // c per ta slot (padded to 8)

// ---------------------------------------------------------------------------
// Kernel 1: top-64 of c_score[128] (stable tie-break) + branch bookkeeping.
// ---------------------------------------------------------------------------
__global__ void sel_k(const float* __restrict__ cs) {
    __shared__ int s_src[64];
    int j = threadIdx.x;                 // 0..127
    float key = cs[j];
    int rank = 0;
#pragma unroll 16
    for (int i = 0; i < 128; i++) {
        float vi = cs[i];
        rank += (vi > key || (vi == key && i < j)) ? 1 : 0;
    }
    if (rank < 64) {
        s_src[rank]   = j;
        g_src[rank]   = j;
        g_scale[rank] = 1.0f / (1.0f + expf(-key));
    }
    __syncthreads();
    if (j == 0) {
        int n3 = 0;
        for (int s = 0; s < 64; s++) {
            int src = s_src[s];
            int br = src >> 5;           // 0..3
            int c  = src & 31;
            g_br[s] = br;
            g_c[s]  = c;
            int slot = 0;
            if (br == 3) { slot = n3; g_list3[n3++] = c; }
            g_slot[s] = slot;
        }
        int p3 = (n3 + 7) & ~7;
        for (int i = n3; i < p3; i++) g_list3[i] = n3 ? g_list3[0] : 0;
        g_ng3 = p3 >> 3;
    }
}

// ---------------------------------------------------------------------------
// Kernel 2: fully fused block. 16x16 tile, 256 threads, 1 block/SM.
// smem: xs 64x18x18, t1s 32x18x18 (full), tas <=32x18x18 (selected avg),
//       staged 1x1 weights, per-warp 3x3 weight buffers.
// ---------------------------------------------------------------------------
#define OFF_XS   0
#define OFF_T1S  (OFF_XS  + CIN*PP)        // 20736
#define OFF_TAS  (OFF_T1S + MID*PP)        // +10368
#define OFF_W31  (OFF_TAS + MID*PP)        // +10368
#define OFF_WAVG (OFF_W31 + MID*CIN)       // +2048
#define OFF_WBUF (OFF_WAVG+ MID*CIN)       // +2048
#define SMEM_FLOATS (OFF_WBUF + 8*CIN*9)   // + 8*576 = 50176
#define SMEM_BYTES  (SMEM_FLOATS * 4)      // 200704

extern __shared__ float smem[];

__global__ __launch_bounds__(256, 1)
void fused_k(const float* __restrict__ x,
             const float* __restrict__ w_main, const float* __restrict__ bn_main,
             const float* __restrict__ w_1x1,  const float* __restrict__ bn_1x1,
             const float* __restrict__ w31,    const float* __restrict__ bn31,
             const float* __restrict__ w32,    const float* __restrict__ bn32,
             const float* __restrict__ wavg,   const float* __restrict__ bnavg1,
             const float* __restrict__ bnavg2,
             float* __restrict__ out)
{
    float* xs    = smem + OFF_XS;
    float* t1s   = smem + OFF_T1S;
    float* tas   = smem + OFF_TAS;
    float* w31s  = smem + OFF_W31;
    float* wavgs = smem + OFF_WAVG;
    float* wbufA = smem + OFF_WBUF;

    const int tid = threadIdx.x;
    const int b   = blockIdx.z;
    const int h0  = blockIdx.y * TS;
    const int w0  = blockIdx.x * TS;

    // ---------- phase 0: stage x patch + 1x1 weights ----------
    const float* xb = x + (size_t)b * CIN * HH * WW;
    for (int i = tid; i < CIN * PP; i += 256) {
        int ic = i / PP;
        int p  = i - ic * PP;
        int py = p / PS, px = p - py * PS;
        int gh = h0 + py - 1, gw = w0 + px - 1;
        float v = 0.0f;
        if ((unsigned)gh < HH && (unsigned)gw < WW)
            v = xb[(ic * HH + gh) * WW + gw];
        xs[i] = v;
    }
    for (int i = tid; i < MID * CIN; i += 256) {
        w31s[i]  = w31[i];
        wavgs[i] = wavg[i];
    }
    __syncthreads();

    // ---------- phase 1: t1 (all 32 ch) and ta (selected avg ch) ----------
    // each thread: pixels p1 = tid, p2 = tid+256 (valid iff tid < 68); 8 oc per group
    {
        const int p1 = tid;
        const bool has2 = (tid < PP - 256);      // tid < 68
        const int p2 = has2 ? (tid + 256) : tid; // clamped for safe loads
        int py1 = p1 / PS, px1 = p1 - py1 * PS;
        int py2 = p2 / PS, px2 = p2 - py2 * PS;
        bool in1 = ((unsigned)(h0 + py1 - 1) < HH) && ((unsigned)(w0 + px1 - 1) < WW);
        bool in2 = ((unsigned)(h0 + py2 - 1) < HH) && ((unsigned)(w0 + px2 - 1) < WW);

        const int ng3 = g_ng3;
        const int ngroups = 4 + ng3;             // 4 t1 groups (32 oc) + ta groups
        for (int grp = 0; grp < ngroups; grp++) {
            bool isT1 = (grp < 4);
            int gi = isT1 ? grp : (grp - 4);
            const float* wsm = isT1 ? w31s : wavgs;
            const float* bnp = isT1 ? bn31 : bnavg1;
            float* dst = isT1 ? t1s : tas;

            int cc[8];
#pragma unroll
            for (int jj = 0; jj < 8; jj++)
                cc[jj] = isT1 ? (gi * 8 + jj) : g_list3[gi * 8 + jj];

            float acc1[8], acc2[8];
#pragma unroll
            for (int jj = 0; jj < 8; jj++) { acc1[jj] = 0.f; acc2[jj] = 0.f; }

#pragma unroll 4
            for (int ic = 0; ic < CIN; ic++) {
                float x1 = xs[ic * PP + p1];
                float x2 = xs[ic * PP + p2];
#pragma unroll
                for (int jj = 0; jj < 8; jj++) {
                    float wv = wsm[cc[jj] * CIN + ic];
                    acc1[jj] += x1 * wv;
                    acc2[jj] += x2 * wv;
                }
            }
#pragma unroll
            for (int jj = 0; jj < 8; jj++) {
                int c = cc[jj];
                float g  = __ldg(bnp + c),      be = __ldg(bnp + 32 + c);
                float m  = __ldg(bnp + 64 + c), vv = __ldg(bnp + 96 + c);
                float inv  = g * rsqrtf(vv + BN_EPS);
                float bias = be - m * inv;
                int slot = gi * 8 + jj;
                dst[slot * PP + p1] = in1 ? (acc1[jj] * inv + bias) : 0.0f;
                if (has2)
                    dst[slot * PP + p2] = in2 ? (acc2[jj] * inv + bias) : 0.0f;
            }
        }
    }
    __syncthreads();

    // ---------- phase 2: one warp per selected channel, 8 px vertical strip/lane ----------
    const int warp = tid >> 5, lane = tid & 31;
    const int c16 = lane & 15;          // output column within tile
    const int rg  = lane >> 4;          // row group (0/1)
    const int r0  = rg * 8;             // first output row of strip
    float* wb = wbufA + warp * (CIN * 9);
    float* outb = out + (size_t)b * 64 * HH * WW;

    for (int k8 = 0; k8 < 8; k8++) {
        const int s = k8 * 8 + warp;    // selected output channel index
        const int br = g_br[s];
        const int c  = g_c[s];
        const float scale = g_scale[s];

        float acc[8];
#pragma unroll
        for (int k = 0; k < 8; k++) acc[k] = 0.f;
        const float* bnp;

        if (br == 0) {
            // main 3x3 over xs (64 ic)
            const float* wsrc = w_main + c * CIN * 9;
            for (int i = lane; i < CIN * 9; i += 32) wb[i] = __ldg(wsrc + i);
            __syncwarp();
            for (int ic = 0; ic < CIN; ic++) {
                const float* wr = wb + ic * 9;
                float q0 = wr[0], q1 = wr[1], q2 = wr[2];
                float q3 = wr[3], q4 = wr[4], q5 = wr[5];
                float q6 = wr[6], q7 = wr[7], q8 = wr[8];
                const float* xc = xs + ic * PP + r0 * PS + c16;
#pragma unroll
                for (int j = 0; j < 10; j++) {
                    float x0 = xc[j * PS], x1 = xc[j * PS + 1], x2 = xc[j * PS + 2];
                    if (j < 8)           acc[j]     += x0 * q0 + x1 * q1 + x2 * q2;
                    if (j >= 1 && j < 9) acc[j - 1] += x0 * q3 + x1 * q4 + x2 * q5;
                    if (j >= 2)          acc[j - 2] += x0 * q6 + x1 * q7 + x2 * q8;
                }
            }
            bnp = bn_main;
        } else if (br == 1) {
            // 1x1 over xs
            const float* wsrc = w_1x1 + c * CIN;
            for (int i = lane; i < CIN; i += 32) wb[i] = __ldg(wsrc + i);
            __syncwarp();
            const int pc = (r0 + 1) * PS + (c16 + 1);
#pragma unroll 4
            for (int ic = 0; ic < CIN; ic++) {
                float wv = wb[ic];
                const float* xc = xs + ic * PP + pc;
#pragma unroll
                for (int k = 0; k < 8; k++)
                    acc[k] += xc[k * PS] * wv;
            }
            bnp = bn_1x1;
        } else if (br == 2) {
            // inner 3x3 over t1s (32 ic)
            const float* wsrc = w32 + c * MID * 9;
            for (int i = lane; i < MID * 9; i += 32) wb[i] = __ldg(wsrc + i);
            __syncwarp();
            for (int ic = 0; ic < MID; ic++) {
                const float* wr = wb + ic * 9;
                float q0 = wr[0], q1 = wr[1], q2 = wr[2];
                float q3 = wr[3], q4 = wr[4], q5 = wr[5];
                float q6 = wr[6], q7 = wr[7], q8 = wr[8];
                const float* xc = t1s + ic * PP + r0 * PS + c16;
#pragma unroll
                for (int j = 0; j < 10; j++) {
                    float x0 = xc[j * PS], x1 = xc[j * PS + 1], x2 = xc[j * PS + 2];
                    if (j < 8)           acc[j]     += x0 * q0 + x1 * q1 + x2 * q2;
                    if (j >= 1 && j < 9) acc[j - 1] += x0 * q3 + x1 * q4 + x2 * q5;
                    if (j >= 2)          acc[j - 2] += x0 * q6 + x1 * q7 + x2 * q8;
                }
            }
            bnp = bn32;
        } else {
            // avgpool 3x3 over selected ta slot
            const int slot = g_slot[s];
            const float* tc = tas + slot * PP + r0 * PS + c16;
            float rs[10];
#pragma unroll
            for (int j = 0; j < 10; j++)
                rs[j] = tc[j * PS] + tc[j * PS + 1] + tc[j * PS + 2];
#pragma unroll
            for (int k = 0; k < 8; k++)
                acc[k] = (rs[k] + rs[k + 1] + rs[k + 2]) * (1.0f / 9.0f);
            bnp = bnavg2;
        }

        float g  = __ldg(bnp + c),      be = __ldg(bnp + 32 + c);
        float m  = __ldg(bnp + 64 + c), vv = __ldg(bnp + 96 + c);
        float inv  = g * rsqrtf(vv + BN_EPS);
        float bias = be - m * inv;

        float* op = outb + ((size_t)s * HH + (h0 + r0)) * WW + (w0 + c16);
#pragma unroll
        for (int k = 0; k < 8; k++)
            op[k * WW] = (acc[k] * inv + bias) * scale;
        // no block sync needed: wbuf slice is warp-private
    }
}

// ---------------------------------------------------------------------------
extern "C" void kernel_launch(void* const* d_in, const int* in_sizes, int n_in,
                              void* d_out, int out_size) {
    const float* x       = (const float*)d_in[0];
    const float* w_main  = (const float*)d_in[1];
    const float* bn_main = (const float*)d_in[2];
    const float* w_1x1   = (const float*)d_in[3];
    const float* bn_1x1  = (const float*)d_in[4];
    const float* w31     = (const float*)d_in[5];
    const float* bn31    = (const float*)d_in[6];
    const float* w32     = (const float*)d_in[7];
    const float* bn32    = (const float*)d_in[8];
    const float* wavg    = (const float*)d_in[9];
    const float* bnavg1  = (const float*)d_in[10];
    const float* bnavg2  = (const float*)d_in[11];
    const float* c_score = (const float*)d_in[12];
    float* out = (float*)d_out;

    static int cfg_done = 0;
    if (!cfg_done) {
        cudaFuncSetAttribute(fused_k, cudaFuncAttributeMaxDynamicSharedMemorySize, SMEM_BYTES);
        cfg_done = 1;
    }

    sel_k<<<1, 128>>>(c_score);

    dim3 grid(WW / TS, HH / TS, BSZ);
    fused_k<<<grid, 256, SMEM_BYTES>>>(x, w_main, bn_main, w_1x1, bn_1x1,
                                       w31, bn31, w32, bn32,
                                       wavg, bnavg1, bnavg2, out);
}

// round 3
// speedup vs baseline: 3.4091x; 1.5187x over previous
#include <cuda_runtime.h>
#include <math.h>

#define BSZ 8
#define CIN 64
#define MID 32
#define HH 256
#define WW 256
#define TS 16
#define PS 18
#define PP 324
#define BN_EPS 1e-5f
#define NWARP 16
#define WBSTRIDE 12           // padded 3x3 weight row (9 -> 12 floats, 48B)

// ---- selection + schedule metadata (sel_k -> fused_k) ----
__device__ int   g_br[64];
__device__ int   g_c[64];
__device__ float g_scale[64];
__device__ int   g_slot[64];      // tas slot for br3 channels
__device__ int   g_list3[40];     // channel per tas slot (padded to mult of 8)
__device__ int   g_schedA[NWARP];         // one item per warp (-1 = idle)
__device__ int   g_schedB[NWARP][24];
__device__ int   g_cntB[NWARP];

// item codes: 0..63 output channel s; 64..67 t1 prep group; 68..71 ta prep group

// ---------------------------------------------------------------------------
// Kernel 1: top-64 (stable) + branch bookkeeping + LPT schedule
// ---------------------------------------------------------------------------
__global__ void sel_k(const float* __restrict__ cs) {
    __shared__ int s_src[64];
    int j = threadIdx.x;                 // 0..127
    float key = cs[j];
    int rank = 0;
#pragma unroll 16
    for (int i = 0; i < 128; i++) {
        float vi = cs[i];
        rank += (vi > key || (vi == key && i < j)) ? 1 : 0;
    }
    if (rank < 64) {
        s_src[rank]   = j;
        g_scale[rank] = 1.0f / (1.0f + expf(-key));
    }
    __syncthreads();
    if (j == 0) {
        int l0[64], n0 = 0, l1[64], n1 = 0, l2[64], n2 = 0, l3[64], n3i = 0;
        int n3 = 0;
        for (int s = 0; s < 64; s++) {
            int src = s_src[s];
            int br = src >> 5, c = src & 31;
            g_br[s] = br; g_c[s] = c; g_slot[s] = 0;
            if (br == 0) l0[n0++] = s;
            else if (br == 1) l1[n1++] = s;
            else if (br == 2) l2[n2++] = s;
            else { g_slot[s] = n3; g_list3[n3++] = c; l3[n3i++] = s; }
        }
        int p3 = (n3 + 7) & ~7;
        for (int i = n3; i < p3; i++) g_list3[i] = n3 ? g_list3[0] : 0;
        int ng3 = p3 >> 3;

        // phase A: prep items on warps 0..prepcount-1, then one br0 (or br1) each
        int prepcount = 4 + ng3;
        int u0 = 0, u1 = 0;
        for (int w = 0; w < NWARP; w++) {
            int it = -1;
            if (w < prepcount)       it = (w < 4) ? (64 + w) : (68 + (w - 4));
            else if (u0 < n0)        it = l0[u0++];
            else if (u1 < n1)        it = l1[u1++];
            g_schedA[w] = it;
        }
        // phase B pool (already cost-descending: br0, br2, br1, br3)
        int pool[64], cost[64], pc = 0;
        for (int i = u0; i < n0; i++) { pool[pc] = l0[i]; cost[pc++] = 6900; }
        for (int i = 0;  i < n2; i++) { pool[pc] = l2[i]; cost[pc++] = 3500; }
        for (int i = u1; i < n1; i++) { pool[pc] = l1[i]; cost[pc++] = 1300; }
        for (int i = 0;  i < n3i; i++){ pool[pc] = l3[i]; cost[pc++] = 100; }
        int load[NWARP], cnt[NWARP];
        for (int w = 0; w < NWARP; w++) { load[w] = 0; cnt[w] = 0; }
        for (int k = 0; k < pc; k++) {
            int wm = 0;
            for (int w = 1; w < NWARP; w++) if (load[w] < load[wm]) wm = w;
            g_schedB[wm][cnt[wm]++] = pool[k];
            load[wm] += cost[k];
        }
        for (int w = 0; w < NWARP; w++) g_cntB[w] = cnt[w];
    }
}

// ---------------------------------------------------------------------------
// smem layout
// ---------------------------------------------------------------------------
#define OFF_XS   0
#define OFF_T1S  (OFF_XS  + CIN*PP)            // 20736
#define OFF_TAS  (OFF_T1S + MID*PP)            // +10368
#define OFF_WBUF (OFF_TAS + MID*PP)            // +10368
#define SMEM_FLOATS (OFF_WBUF + NWARP*CIN*WBSTRIDE)   // +16*768 = 53760
#define SMEM_BYTES  (SMEM_FLOATS * 4)                 // 215040

extern __shared__ float smem[];

// ---------------------------------------------------------------------------
// warp-level work item
// ---------------------------------------------------------------------------
__device__ __forceinline__ void run_item(
    int code, int lane,
    float* xs, float* t1s, float* tas, float* wb,
    const float* __restrict__ w_main, const float* __restrict__ bn_main,
    const float* __restrict__ w_1x1,  const float* __restrict__ bn_1x1,
    const float* __restrict__ w31,    const float* __restrict__ bn31,
    const float* __restrict__ w32,    const float* __restrict__ bn32,
    const float* __restrict__ wavg,   const float* __restrict__ bnavg1,
    const float* __restrict__ bnavg2,
    float* outb, int h0, int w0)
{
    if (code >= 64) {
        // ---------- prep item: 1x1 conv + BN over the 18x18 patch, 8 oc ----------
        bool isT1 = (code < 68);
        int gi = isT1 ? (code - 64) : (code - 68);
        const float* wg  = isT1 ? w31 : wavg;
        const float* bnp = isT1 ? bn31 : bnavg1;
        float* dst = isT1 ? t1s : tas;

        int ch[8];
#pragma unroll
        for (int jj = 0; jj < 8; jj++)
            ch[jj] = isT1 ? (gi * 8 + jj) : g_list3[gi * 8 + jj];

        float inv8[8], bias8[8];
#pragma unroll
        for (int jj = 0; jj < 8; jj++) {
            int c = ch[jj];
            float g = __ldg(bnp + c),      be = __ldg(bnp + 32 + c);
            float m = __ldg(bnp + 64 + c), v  = __ldg(bnp + 96 + c);
            float iv = g * rsqrtf(v + BN_EPS);
            inv8[jj] = iv; bias8[jj] = be - m * iv;
        }

        for (int pass = 0; pass < 3; pass++) {
            int p0 = pass * 128 + lane * 4;
            int pc = (p0 > PP - 4) ? (PP - 4) : p0;    // safe load base
            bool inq[4];
#pragma unroll
            for (int q = 0; q < 4; q++) {
                int p = p0 + q;
                int py = p / PS, px = p - py * PS;
                inq[q] = (p < PP) &&
                         ((unsigned)(h0 + py - 1) < HH) &&
                         ((unsigned)(w0 + px - 1) < WW);
            }
#pragma unroll
            for (int half = 0; half < 2; half++) {
                float acc[4][4];
#pragma unroll
                for (int a = 0; a < 4; a++)
#pragma unroll
                    for (int b = 0; b < 4; b++) acc[a][b] = 0.0f;

#pragma unroll 4
                for (int icg = 0; icg < CIN / 4; icg++) {
                    float4 x0 = *(const float4*)(xs + (icg * 4 + 0) * PP + pc);
                    float4 x1 = *(const float4*)(xs + (icg * 4 + 1) * PP + pc);
                    float4 x2 = *(const float4*)(xs + (icg * 4 + 2) * PP + pc);
                    float4 x3 = *(const float4*)(xs + (icg * 4 + 3) * PP + pc);
#pragma unroll
                    for (int jj = 0; jj < 4; jj++) {
                        float4 wq = __ldg((const float4*)(wg + ch[half * 4 + jj] * CIN + icg * 4));
                        acc[jj][0] += wq.x * x0.x + wq.y * x1.x + wq.z * x2.x + wq.w * x3.x;
                        acc[jj][1] += wq.x * x0.y + wq.y * x1.y + wq.z * x2.y + wq.w * x3.y;
                        acc[jj][2] += wq.x * x0.z + wq.y * x1.z + wq.z * x2.z + wq.w * x3.z;
                        acc[jj][3] += wq.x * x0.w + wq.y * x1.w + wq.z * x2.w + wq.w * x3.w;
                    }
                }
#pragma unroll
                for (int jj = 0; jj < 4; jj++) {
                    int j8 = half * 4 + jj;
                    int slot = gi * 8 + j8;
#pragma unroll
                    for (int q = 0; q < 4; q++) {
                        int p = p0 + q;
                        if (p < PP)
                            dst[slot * PP + p] = inq[q] ? (acc[jj][q] * inv8[j8] + bias8[j8])
                                                        : 0.0f;
                    }
                }
            }
        }
        return;
    }

    // ---------- output item: one selected channel over the 16x16 tile ----------
    const int s = code;
    const int br = g_br[s];
    const int c  = g_c[s];
    const float scale = g_scale[s];
    const int c16 = lane & 15, rg = lane >> 4, r0 = rg * 8;

    float acc[8];
#pragma unroll
    for (int k = 0; k < 8; k++) acc[k] = 0.0f;
    const float* bnp;

    __syncwarp();
    if (br == 0 || br == 2) {
        const int CH = (br == 0) ? CIN : MID;
        const float* wsrc = (br == 0) ? (w_main + c * CIN * 9) : (w32 + c * MID * 9);
        const float* srcp = (br == 0) ? xs : t1s;
        bnp = (br == 0) ? bn_main : bn32;
        for (int i = lane; i < CH * 9; i += 32)
            wb[(i / 9) * WBSTRIDE + (i % 9)] = __ldg(wsrc + i);
        __syncwarp();
#pragma unroll 2
        for (int ic = 0; ic < CH; ic++) {
            const float4* wr4 = (const float4*)(wb + ic * WBSTRIDE);
            float4 wA = wr4[0], wB = wr4[1];
            float q8 = wb[ic * WBSTRIDE + 8];
            const float* xc = srcp + ic * PP + r0 * PS + c16;
#pragma unroll
            for (int j = 0; j < 10; j++) {
                float x0 = xc[j * PS], x1 = xc[j * PS + 1], x2 = xc[j * PS + 2];
                if (j < 8)            acc[j]     += x0 * wA.x + x1 * wA.y + x2 * wA.z;
                if (j >= 1 && j < 9)  acc[j - 1] += x0 * wA.w + x1 * wB.x + x2 * wB.y;
                if (j >= 2)           acc[j - 2] += x0 * wB.z + x1 * wB.w + x2 * q8;
            }
        }
    } else if (br == 1) {
        bnp = bn_1x1;
        const float* wsrc = w_1x1 + c * CIN;
        for (int i = lane; i < CIN; i += 32) wb[i] = __ldg(wsrc + i);
        __syncwarp();
        const int pcx = (r0 + 1) * PS + (c16 + 1);
#pragma unroll 4
        for (int ic = 0; ic < CIN; ic++) {
            float wv = wb[ic];
            const float* xc = xs + ic * PP + pcx;
#pragma unroll
            for (int k = 0; k < 8; k++)
                acc[k] += xc[k * PS] * wv;
        }
    } else {
        bnp = bnavg2;
        const int slot = g_slot[s];
        const float* tc = tas + slot * PP + r0 * PS + c16;
        float rs[10];
#pragma unroll
        for (int j = 0; j < 10; j++)
            rs[j] = tc[j * PS] + tc[j * PS + 1] + tc[j * PS + 2];
#pragma unroll
        for (int k = 0; k < 8; k++)
            acc[k] = (rs[k] + rs[k + 1] + rs[k + 2]) * (1.0f / 9.0f);
    }

    float g  = __ldg(bnp + c),      be = __ldg(bnp + 32 + c);
    float m  = __ldg(bnp + 64 + c), v  = __ldg(bnp + 96 + c);
    float iv = g * rsqrtf(v + BN_EPS);
    float bias = be - m * iv;

    float* op = outb + ((size_t)s * HH + (h0 + r0)) * WW + (w0 + c16);
#pragma unroll
    for (int k = 0; k < 8; k++)
        op[k * WW] = (acc[k] * iv + bias) * scale;
}

// ---------------------------------------------------------------------------
__global__ __launch_bounds__(512, 1)
void fused_k(const float* __restrict__ x,
             const float* __restrict__ w_main, const float* __restrict__ bn_main,
             const float* __restrict__ w_1x1,  const float* __restrict__ bn_1x1,
             const float* __restrict__ w31,    const float* __restrict__ bn31,
             const float* __restrict__ w32,    const float* __restrict__ bn32,
             const float* __restrict__ wavg,   const float* __restrict__ bnavg1,
             const float* __restrict__ bnavg2,
             float* __restrict__ out)
{
    float* xs    = smem + OFF_XS;
    float* t1s   = smem + OFF_T1S;
    float* tas   = smem + OFF_TAS;
    float* wbufA = smem + OFF_WBUF;

    const int tid  = threadIdx.x;
    const int warp = tid >> 5, lane = tid & 31;
    const int b  = blockIdx.z;
    const int h0 = blockIdx.y * TS;
    const int w0 = blockIdx.x * TS;

    // ---------- phase 0: stage x patch ----------
    const float* xb = x + (size_t)b * CIN * HH * WW;
    for (int i = tid; i < CIN * PP; i += 512) {
        int ic = i / PP;
        int p  = i - ic * PP;
        int py = p / PS, px = p - py * PS;
        int gh = h0 + py - 1, gw = w0 + px - 1;
        float v = 0.0f;
        if ((unsigned)gh < HH && (unsigned)gw < WW)
            v = xb[(ic * HH + gh) * WW + gw];
        xs[i] = v;
    }
    __syncthreads();

    float* wb = wbufA + warp * (CIN * WBSTRIDE);
    float* outb = out + (size_t)b * 64 * HH * WW;

    // ---------- phase A ----------
    int itA = g_schedA[warp];
    if (itA >= 0)
        run_item(itA, lane, xs, t1s, tas, wb,
                 w_main, bn_main, w_1x1, bn_1x1, w31, bn31, w32, bn32,
                 wavg, bnavg1, bnavg2, outb, h0, w0);
    __syncthreads();

    // ---------- phase B ----------
    int cnt = g_cntB[warp];
    for (int i = 0; i < cnt; i++)
        run_item(g_schedB[warp][i], lane, xs, t1s, tas, wb,
                 w_main, bn_main, w_1x1, bn_1x1, w31, bn31, w32, bn32,
                 wavg, bnavg1, bnavg2, outb, h0, w0);
}

// ---------------------------------------------------------------------------
extern "C" void kernel_launch(void* const* d_in, const int* in_sizes, int n_in,
                              void* d_out, int out_size) {
    const float* x       = (const float*)d_in[0];
    const float* w_main  = (const float*)d_in[1];
    const float* bn_main = (const float*)d_in[2];
    const float* w_1x1   = (const float*)d_in[3];
    const float* bn_1x1  = (const float*)d_in[4];
    const float* w31     = (const float*)d_in[5];
    const float* bn31    = (const float*)d_in[6];
    const float* w32     = (const float*)d_in[7];
    const float* bn32    = (const float*)d_in[8];
    const float* wavg    = (const float*)d_in[9];
    const float* bnavg1  = (const float*)d_in[10];
    const float* bnavg2  = (const float*)d_in[11];
    const float* c_score = (const float*)d_in[12];
    float* out = (float*)d_out;

    static int cfg_done = 0;
    if (!cfg_done) {
        cudaFuncSetAttribute(fused_k, cudaFuncAttributeMaxDynamicSharedMemorySize, SMEM_BYTES);
        cfg_done = 1;
    }

    sel_k<<<1, 128>>>(c_score);

    dim3 grid(WW / TS, HH / TS, BSZ);
    fused_k<<<grid, 512, SMEM_BYTES>>>(x, w_main, bn_main, w_1x1, bn_1x1,
                                       w31, bn31, w32, bn32,
                                       wavg, bnavg1, bnavg2, out);
}

// round 4
// speedup vs baseline: 4.0034x; 1.1743x over previous
#include <cuda_runtime.h>
#include <math.h>

typedef unsigned long long ull;

#define BSZ 8
#define CIN 64
#define MID 32
#define HH 256
#define WW 256
#define TS 16
#define PS 18
#define PP 324
#define BN_EPS 1e-5f
#define NWARP 16

// ---------------- f32x2 helpers ----------------
#define FMA2(a, x, w) asm("fma.rn.f32x2 %0, %1, %2, %0;" : "+l"(a) : "l"(x), "l"(w))
__device__ __forceinline__ ull pk2(float x) {
    ull d; unsigned u = __float_as_uint(x);
    asm("mov.b64 %0, {%1, %1};" : "=l"(d) : "r"(u)); return d;
}
__device__ __forceinline__ ull pk2b(float lo, float hi) {
    ull d;
    asm("mov.b64 %0, {%1, %2};" : "=l"(d) : "r"(__float_as_uint(lo)), "r"(__float_as_uint(hi)));
    return d;
}
__device__ __forceinline__ void upk(ull v, float& lo, float& hi) {
    unsigned a, b;
    asm("mov.b64 {%0, %1}, %2;" : "=r"(a), "=r"(b) : "l"(v));
    lo = __uint_as_float(a); hi = __uint_as_float(b);
}

// ---------------- selection / schedule metadata ----------------
__device__ float g_scale[64];
__device__ int   g_slot[64];
__device__ int   g_list3[40];

#define MAXIT 80
__device__ int g_it_kind[MAXIT];   // 0 br0-pair, 1 br1-pair, 2 br2-pair, 3 avg-single, 4 t1-prep, 5 ta-prep
__device__ int g_it_a[MAXIT];      // s0 (or prep group)
__device__ int g_it_b[MAXIT];      // s1
__device__ int g_it_c0[MAXIT];
__device__ int g_it_c1[MAXIT];
__device__ int g_it_off[MAXIT];    // float offset into g_wpack
__device__ int g_nit;

__device__ int g_schedA[NWARP][8], g_cntA[NWARP];
__device__ int g_schedB[NWARP][12], g_cntB[NWARP];

__device__ float g_wpack[36864 + 2048];   // paired weights + prefetch-tail pad

// ---------------------------------------------------------------------------
// Kernel 1: top-64 (stable), pairing, pack descriptors, LPT schedule
// ---------------------------------------------------------------------------
__global__ void sel_k(const float* __restrict__ cs) {
    __shared__ int s_src[64];
    int j = threadIdx.x;                 // 0..127
    float key = cs[j];
    int rank = 0;
#pragma unroll 16
    for (int i = 0; i < 128; i++) {
        float vi = cs[i];
        rank += (vi > key || (vi == key && i < j)) ? 1 : 0;
    }
    if (rank < 64) {
        s_src[rank]   = j;
        g_scale[rank] = 1.0f / (1.0f + expf(-key));
    }
    __syncthreads();
    if (j != 0) return;

    int l[4][64], n[4] = {0, 0, 0, 0};
    int cc[64];
    int n3 = 0;
    for (int s = 0; s < 64; s++) {
        int src = s_src[s];
        int br = src >> 5, c = src & 31;
        cc[s] = c;
        g_slot[s] = 0;
        if (br == 3) { g_slot[s] = n3; g_list3[n3++] = c; }
        l[br][n[br]++] = s;
    }
    int p3 = (n3 + 7) & ~7;
    for (int i = n3; i < p3; i++) g_list3[i] = n3 ? g_list3[0] : 0;
    int ng3 = p3 >> 3;

    // ---- build item table ----
    int nit = 0;
    if (n[2] > 0)
        for (int g = 0; g < 4; g++) { g_it_kind[nit] = 4; g_it_a[nit] = g; nit++; }
    if (n3 > 0)
        for (int g = 0; g < ng3; g++) { g_it_kind[nit] = 5; g_it_a[nit] = g; nit++; }

    int wo = 0;
    // br0 pairs (stride 64*20=1280), br2 pairs (32*20=640), br1 pairs (64*2=128)
    const int strides[3] = {1280, 128, 640};
    for (int br = 0; br < 3; br++) {
        for (int i = 0; i < n[br]; i += 2) {
            int s0 = l[br][i];
            int s1 = (i + 1 < n[br]) ? l[br][i + 1] : s0;
            g_it_kind[nit] = br;
            g_it_a[nit] = s0; g_it_b[nit] = s1;
            g_it_c0[nit] = cc[s0]; g_it_c1[nit] = cc[s1];
            g_it_off[nit] = wo;
            wo += strides[br];
            nit++;
        }
    }
    for (int i = 0; i < n[3]; i++) {
        g_it_kind[nit] = 3; g_it_a[nit] = l[3][i]; nit++;
    }
    g_nit = nit;

    // ---- LPT schedules ----
    const int costk[6] = {9300, 1700, 4800, 150, 5600, 5600};
    int lA[NWARP], cA[NWARP], lB[NWARP], cB[NWARP];
    for (int w = 0; w < NWARP; w++) { lA[w] = 0; cA[w] = 0; lB[w] = 0; cB[w] = 0; }
    // A-eligible order: br0, prep, br1 ; B order: br2, br3
    const int orderA[3] = {0, 4, 1};         // (5 handled with 4)
    for (int oi = 0; oi < 3; oi++) {
        int kk = orderA[oi];
        for (int i = 0; i < nit; i++) {
            int kd = g_it_kind[i];
            bool match = (kk == 4) ? (kd == 4 || kd == 5) : (kd == kk);
            if (!match) continue;
            int wm = 0;
            for (int w = 1; w < NWARP; w++) if (lA[w] < lA[wm]) wm = w;
            if (cA[wm] < 8) { g_schedA[wm][cA[wm]++] = i; lA[wm] += costk[kd]; }
        }
    }
    const int orderB[2] = {2, 3};
    for (int oi = 0; oi < 2; oi++) {
        int kk = orderB[oi];
        for (int i = 0; i < nit; i++) {
            if (g_it_kind[i] != kk) continue;
            int wm = 0;
            for (int w = 1; w < NWARP; w++) if (lB[w] < lB[wm]) wm = w;
            if (cB[wm] < 12) { g_schedB[wm][cB[wm]++] = i; lB[wm] += costk[kk]; }
        }
    }
    for (int w = 0; w < NWARP; w++) { g_cntA[w] = cA[w]; g_cntB[w] = cB[w]; }
}

// ---------------------------------------------------------------------------
// Kernel 2: pack paired weights into g_wpack
// layout per pair item: [ic][20 floats] = (w0a,w0b, w1a,w1b, ..., w8a,w8b, pad, pad)
// br1 item: [ic][2] = (wa, wb)
// ---------------------------------------------------------------------------
__global__ void pack_k(const float* __restrict__ w_main,
                       const float* __restrict__ w_1x1,
                       const float* __restrict__ w32) {
    int it = blockIdx.x;
    if (it >= g_nit) return;
    int kind = g_it_kind[it];
    if (kind >= 3) return;
    int c0 = g_it_c0[it], c1 = g_it_c1[it];
    int off = g_it_off[it];
    int tid = threadIdx.x;
    if (kind == 1) {
        if (tid < 64) {
            g_wpack[off + 2 * tid]     = w_1x1[c0 * 64 + tid];
            g_wpack[off + 2 * tid + 1] = w_1x1[c1 * 64 + tid];
        }
        return;
    }
    int CH = (kind == 0) ? CIN : MID;
    const float* src = (kind == 0) ? w_main : w32;
    for (int e = tid; e < CH * 9; e += blockDim.x) {
        int ic = e / 9, r = e - ic * 9;
        g_wpack[off + ic * 20 + 2 * r]     = src[c0 * CH * 9 + e];
        g_wpack[off + ic * 20 + 2 * r + 1] = src[c1 * CH * 9 + e];
    }
}

// ---------------------------------------------------------------------------
// smem layout (no weight buffers anymore)
// ---------------------------------------------------------------------------
#define OFF_XS   0
#define OFF_T1S  (OFF_XS  + CIN*PP)
#define OFF_TAS  (OFF_T1S + MID*PP)
#define SMEM_FLOATS (OFF_TAS + MID*PP)     // 41472 floats
#define SMEM_BYTES  (SMEM_FLOATS * 4)      // 165888

extern __shared__ float smem[];

// ---------------------------------------------------------------------------
// paired 3x3 conv over srcp (CH input channels) using f32x2
// ---------------------------------------------------------------------------
__device__ __forceinline__ void conv3x3_pair(
    int s0, int s1, int c0, int c1, int off,
    const float* __restrict__ srcp, int CH, const float* __restrict__ bnp,
    float* outb, int h0, int w0, int lane)
{
    const int c16 = lane & 15, r0 = (lane >> 4) * 8;
    ull acc[8];
#pragma unroll
    for (int k = 0; k < 8; k++) acc[k] = 0ull;

    const ulonglong2* wp = (const ulonglong2*)(g_wpack + off);
    ulonglong2 q0 = wp[0], q1 = wp[1], q2 = wp[2], q3 = wp[3], q4 = wp[4];

#pragma unroll 2
    for (int ic = 0; ic < CH; ic++) {
        // prefetch next ic's weights (pad at tail makes tail read safe)
        const ulonglong2* np = wp + (ic + 1) * 5;
        ulonglong2 n0 = np[0], n1 = np[1], n2 = np[2], n3 = np[3], n4 = np[4];

        ull w0 = q0.x, w1 = q0.y, w2 = q1.x, w3 = q1.y, w4 = q2.x,
            w5 = q2.y, w6 = q3.x, w7 = q3.y, w8 = q4.x;
        const float* xc = srcp + ic * PP + r0 * PS + c16;
#pragma unroll
        for (int j = 0; j < 10; j++) {
            float x0 = xc[j * PS], x1 = xc[j * PS + 1], x2 = xc[j * PS + 2];
            ull d0 = pk2(x0), d1 = pk2(x1), d2 = pk2(x2);
            if (j < 8)            { FMA2(acc[j],     d0, w0); FMA2(acc[j],     d1, w1); FMA2(acc[j],     d2, w2); }
            if (j >= 1 && j < 9)  { FMA2(acc[j - 1], d0, w3); FMA2(acc[j - 1], d1, w4); FMA2(acc[j - 1], d2, w5); }
            if (j >= 2)           { FMA2(acc[j - 2], d0, w6); FMA2(acc[j - 2], d1, w7); FMA2(acc[j - 2], d2, w8); }
        }
        q0 = n0; q1 = n1; q2 = n2; q3 = n3; q4 = n4;
    }

    float g0  = __ldg(bnp + c0),      be0 = __ldg(bnp + 32 + c0);
    float m0  = __ldg(bnp + 64 + c0), v0  = __ldg(bnp + 96 + c0);
    float g1  = __ldg(bnp + c1),      be1 = __ldg(bnp + 32 + c1);
    float m1  = __ldg(bnp + 64 + c1), v1  = __ldg(bnp + 96 + c1);
    float iv0 = g0 * rsqrtf(v0 + BN_EPS), b0 = be0 - m0 * iv0;
    float iv1 = g1 * rsqrtf(v1 + BN_EPS), b1 = be1 - m1 * iv1;
    float sc0 = g_scale[s0], sc1 = g_scale[s1];

    float* op0 = outb + ((size_t)s0 * HH + (h0 + r0)) * WW + (w0 + c16);
    float* op1 = outb + ((size_t)s1 * HH + (h0 + r0)) * WW + (w0 + c16);
#pragma unroll
    for (int k = 0; k < 8; k++) {
        float a0, a1; upk(acc[k], a0, a1);
        op0[k * WW] = (a0 * iv0 + b0) * sc0;
        op1[k * WW] = (a1 * iv1 + b1) * sc1;
    }
}

// ---------------------------------------------------------------------------
__device__ __forceinline__ void run_item(
    int idx, int lane,
    float* xs, float* t1s, float* tas,
    const float* __restrict__ w31,    const float* __restrict__ bn31,
    const float* __restrict__ wavg,   const float* __restrict__ bnavg1,
    const float* __restrict__ bn_main,const float* __restrict__ bn_1x1,
    const float* __restrict__ bn32,   const float* __restrict__ bnavg2,
    float* outb, int h0, int w0)
{
    const int kind = g_it_kind[idx];

    if (kind == 0) {
        conv3x3_pair(g_it_a[idx], g_it_b[idx], g_it_c0[idx], g_it_c1[idx], g_it_off[idx],
                     xs, CIN, bn_main, outb, h0, w0, lane);
        return;
    }
    if (kind == 2) {
        conv3x3_pair(g_it_a[idx], g_it_b[idx], g_it_c0[idx], g_it_c1[idx], g_it_off[idx],
                     t1s, MID, bn32, outb, h0, w0, lane);
        return;
    }
    if (kind == 1) {
        // paired 1x1
        const int s0 = g_it_a[idx], s1 = g_it_b[idx];
        const int c0 = g_it_c0[idx], c1 = g_it_c1[idx];
        const ull* wp = (const ull*)(g_wpack + g_it_off[idx]);
        const int c16 = lane & 15, r0 = (lane >> 4) * 8;
        ull acc[8];
#pragma unroll
        for (int k = 0; k < 8; k++) acc[k] = 0ull;
        const int pcx = (r0 + 1) * PS + (c16 + 1);
#pragma unroll 4
        for (int ic = 0; ic < CIN; ic++) {
            ull wv = __ldg(wp + ic);
            const float* xc = xs + ic * PP + pcx;
#pragma unroll
            for (int k = 0; k < 8; k++) {
                ull xd = pk2(xc[k * PS]);
                FMA2(acc[k], xd, wv);
            }
        }
        float g0  = __ldg(bn_1x1 + c0),      be0 = __ldg(bn_1x1 + 32 + c0);
        float m0  = __ldg(bn_1x1 + 64 + c0), v0  = __ldg(bn_1x1 + 96 + c0);
        float g1  = __ldg(bn_1x1 + c1),      be1 = __ldg(bn_1x1 + 32 + c1);
        float m1  = __ldg(bn_1x1 + 64 + c1), v1  = __ldg(bn_1x1 + 96 + c1);
        float iv0 = g0 * rsqrtf(v0 + BN_EPS), b0 = be0 - m0 * iv0;
        float iv1 = g1 * rsqrtf(v1 + BN_EPS), b1 = be1 - m1 * iv1;
        float sc0 = g_scale[s0], sc1 = g_scale[s1];
        float* op0 = outb + ((size_t)s0 * HH + (h0 + r0)) * WW + (w0 + c16);
        float* op1 = outb + ((size_t)s1 * HH + (h0 + r0)) * WW + (w0 + c16);
#pragma unroll
        for (int k = 0; k < 8; k++) {
            float a0, a1; upk(acc[k], a0, a1);
            op0[k * WW] = (a0 * iv0 + b0) * sc0;
            op1[k * WW] = (a1 * iv1 + b1) * sc1;
        }
        return;
    }
    if (kind == 3) {
        // avg single
        const int s = g_it_a[idx];
        const int c16 = lane & 15, r0 = (lane >> 4) * 8;
        const int slot = g_slot[s];
        const float* tc = tas + slot * PP + r0 * PS + c16;
        float rs[10];
#pragma unroll
        for (int j = 0; j < 10; j++)
            rs[j] = tc[j * PS] + tc[j * PS + 1] + tc[j * PS + 2];
        // channel c for BN
        int c = g_list3[slot];
        float g  = __ldg(bnavg2 + c),      be = __ldg(bnavg2 + 32 + c);
        float m  = __ldg(bnavg2 + 64 + c), v  = __ldg(bnavg2 + 96 + c);
        float iv = g * rsqrtf(v + BN_EPS);
        float bias = be - m * iv;
        float sc = g_scale[s];
        float* op = outb + ((size_t)s * HH + (h0 + r0)) * WW + (w0 + c16);
#pragma unroll
        for (int k = 0; k < 8; k++) {
            float a = (rs[k] + rs[k + 1] + rs[k + 2]) * (1.0f / 9.0f);
            op[k * WW] = (a * iv + bias) * sc;
        }
        return;
    }

    // ---------- prep item (kind 4 = t1 group, kind 5 = ta group) ----------
    {
        bool isT1 = (kind == 4);
        int gi = g_it_a[idx];
        const float* wg  = isT1 ? w31 : wavg;
        const float* bnp = isT1 ? bn31 : bnavg1;
        float* dst = isT1 ? t1s : tas;

        int ch[8];
#pragma unroll
        for (int jj = 0; jj < 8; jj++)
            ch[jj] = isT1 ? (gi * 8 + jj) : g_list3[gi * 8 + jj];

        float inv8[8], bias8[8];
#pragma unroll
        for (int jj = 0; jj < 8; jj++) {
            int c = ch[jj];
            float g = __ldg(bnp + c),      be = __ldg(bnp + 32 + c);
            float m = __ldg(bnp + 64 + c), v  = __ldg(bnp + 96 + c);
            float iv = g * rsqrtf(v + BN_EPS);
            inv8[jj] = iv; bias8[jj] = be - m * iv;
        }

        for (int pass = 0; pass < 3; pass++) {
            int p0 = pass * 128 + lane * 4;
            if (p0 >= PP) continue;
            bool inq[4];
            bool allin = true;
#pragma unroll
            for (int q = 0; q < 4; q++) {
                int p = p0 + q;
                int py = p / PS, px = p - py * PS;
                inq[q] = ((unsigned)(h0 + py - 1) < HH) && ((unsigned)(w0 + px - 1) < WW);
                allin = allin && inq[q];
            }
#pragma unroll
            for (int half = 0; half < 2; half++) {
                ull acc2[4][2];
#pragma unroll
                for (int a = 0; a < 4; a++) { acc2[a][0] = 0ull; acc2[a][1] = 0ull; }

#pragma unroll 4
                for (int icg = 0; icg < CIN / 4; icg++) {
                    ulonglong2 xv0 = *(const ulonglong2*)(xs + (icg * 4 + 0) * PP + p0);
                    ulonglong2 xv1 = *(const ulonglong2*)(xs + (icg * 4 + 1) * PP + p0);
                    ulonglong2 xv2 = *(const ulonglong2*)(xs + (icg * 4 + 2) * PP + p0);
                    ulonglong2 xv3 = *(const ulonglong2*)(xs + (icg * 4 + 3) * PP + p0);
#pragma unroll
                    for (int jj = 0; jj < 4; jj++) {
                        float4 wq = __ldg((const float4*)(wg + ch[half * 4 + jj] * CIN + icg * 4));
                        ull wd0 = pk2(wq.x), wd1 = pk2(wq.y), wd2 = pk2(wq.z), wd3 = pk2(wq.w);
                        FMA2(acc2[jj][0], xv0.x, wd0); FMA2(acc2[jj][1], xv0.y, wd0);
                        FMA2(acc2[jj][0], xv1.x, wd1); FMA2(acc2[jj][1], xv1.y, wd1);
                        FMA2(acc2[jj][0], xv2.x, wd2); FMA2(acc2[jj][1], xv2.y, wd2);
                        FMA2(acc2[jj][0], xv3.x, wd3); FMA2(acc2[jj][1], xv3.y, wd3);
                    }
                }
#pragma unroll
                for (int jj = 0; jj < 4; jj++) {
                    int j8 = half * 4 + jj;
                    int slot = gi * 8 + j8;
                    ull ivd = pk2(inv8[j8]);
                    ull t0 = pk2(bias8[j8]);
                    ull t1 = t0;
                    FMA2(t0, acc2[jj][0], ivd);
                    FMA2(t1, acc2[jj][1], ivd);
                    float* dp = dst + slot * PP + p0;
                    if (allin) {
                        *(ull*)(dp)     = t0;
                        *(ull*)(dp + 2) = t1;
                    } else {
                        float a0, a1, a2, a3;
                        upk(t0, a0, a1); upk(t1, a2, a3);
                        dp[0] = inq[0] ? a0 : 0.0f;
                        dp[1] = inq[1] ? a1 : 0.0f;
                        dp[2] = inq[2] ? a2 : 0.0f;
                        dp[3] = inq[3] ? a3 : 0.0f;
                    }
                }
            }
        }
    }
}

// ---------------------------------------------------------------------------
__global__ __launch_bounds__(512, 1)
void fused_k(const float* __restrict__ x,
             const float* __restrict__ bn_main,
             const float* __restrict__ bn_1x1,
             const float* __restrict__ w31,    const float* __restrict__ bn31,
             const float* __restrict__ bn32,
             const float* __restrict__ wavg,   const float* __restrict__ bnavg1,
             const float* __restrict__ bnavg2,
             float* __restrict__ out)
{
    float* xs  = smem + OFF_XS;
    float* t1s = smem + OFF_T1S;
    float* tas = smem + OFF_TAS;

    const int tid  = threadIdx.x;
    const int warp = tid >> 5, lane = tid & 31;
    const int b  = blockIdx.z;
    const int h0 = blockIdx.y * TS;
    const int w0 = blockIdx.x * TS;

    // ---------- phase 0: stage x patch ----------
    const float* xb = x + (size_t)b * CIN * HH * WW;
    for (int i = tid; i < CIN * PP; i += 512) {
        int ic = i / PP;
        int p  = i - ic * PP;
        int py = p / PS, px = p - py * PS;
        int gh = h0 + py - 1, gw = w0 + px - 1;
        float v = 0.0f;
        if ((unsigned)gh < HH && (unsigned)gw < WW)
            v = xb[(ic * HH + gh) * WW + gw];
        xs[i] = v;
    }
    __syncthreads();

    float* outb = out + (size_t)b * 64 * HH * WW;

    // ---------- phase A ----------
    int ca = g_cntA[warp];
    for (int k = 0; k < ca; k++)
        run_item(g_schedA[warp][k], lane, xs, t1s, tas,
                 w31, bn31, wavg, bnavg1, bn_main, bn_1x1, bn32, bnavg2,
                 outb, h0, w0);
    __syncthreads();

    // ---------- phase B ----------
    int cb = g_cntB[warp];
    for (int k = 0; k < cb; k++)
        run_item(g_schedB[warp][k], lane, xs, t1s, tas,
                 w31, bn31, wavg, bnavg1, bn_main, bn_1x1, bn32, bnavg2,
                 outb, h0, w0);
}

// ---------------------------------------------------------------------------
extern "C" void kernel_launch(void* const* d_in, const int* in_sizes, int n_in,
                              void* d_out, int out_size) {
    const float* x       = (const float*)d_in[0];
    const float* w_main  = (const float*)d_in[1];
    const float* bn_main = (const float*)d_in[2];
    const float* w_1x1   = (const float*)d_in[3];
    const float* bn_1x1  = (const float*)d_in[4];
    const float* w31     = (const float*)d_in[5];
    const float* bn31    = (const float*)d_in[6];
    const float* w32     = (const float*)d_in[7];
    const float* bn32    = (const float*)d_in[8];
    const float* wavg    = (const float*)d_in[9];
    const float* bnavg1  = (const float*)d_in[10];
    const float* bnavg2  = (const float*)d_in[11];
    const float* c_score = (const float*)d_in[12];
    float* out = (float*)d_out;

    static int cfg_done = 0;
    if (!cfg_done) {
        cudaFuncSetAttribute(fused_k, cudaFuncAttributeMaxDynamicSharedMemorySize, SMEM_BYTES);
        cfg_done = 1;
    }

    sel_k<<<1, 128>>>(c_score);
    pack_k<<<MAXIT, 128>>>(w_main, w_1x1, w32);

    dim3 grid(WW / TS, HH / TS, BSZ);
    fused_k<<<grid, 512, SMEM_BYTES>>>(x, bn_main, bn_1x1,
                                       w31, bn31, bn32,
                                       wavg, bnavg1, bnavg2, out);
}